// round 4
// baseline (speedup 1.0000x reference)
#include <cuda_runtime.h>
#include <math.h>

// Problem constants
#define B_    2
#define S_    4096
#define D_    2048
#define H_    16
#define HD_   128
#define C_    64
#define NC_   64
#define M_    (B_*S_)        // 8192 tokens
#define N1_   (5*D_)         // 10240
#define LANES_ (B_*H_*HD_)   // 4096
#define RMS_EPS 1.1920928955078125e-07f

// -------- scratch (static device globals; no runtime allocation) --------
__device__ float g_proj[M_*(size_t)N1_];   // [8192,10240] projection
__device__ float g_mem [M_*(size_t)D_];    // memory states [B*S, D]
__device__ float g_y   [M_*(size_t)D_];    // gated output  [B*S, D]
__device__ float g_Pc  [NC_*LANES_];       // per-chunk cumprod end
__device__ float g_Ac  [NC_*LANES_];       // per-chunk acc end
__device__ float g_S0  [NC_*LANES_];       // chunk-start states

__device__ __forceinline__ float sigmoidf_(float x) {
    return 1.0f / (1.0f + expf(-x));
}

// ======================= SGEMM: C[M,N] = A[M,K] * B[N,K]^T =======================
// A row-major [M,K], B row-major [N,K] (both K-contiguous). 128x128 tile, BK=16,
// 256 threads, 8x8 microtile per thread.
__global__ __launch_bounds__(256) void sgemm_nt(const float* __restrict__ A,
                                                const float* __restrict__ B,
                                                float* __restrict__ C,
                                                int M, int N, int K) {
    __shared__ float As[16][128];
    __shared__ float Bs[16][128];

    const int tid = threadIdx.x;
    const float* Ab = A + (long)blockIdx.y * 128 * K;
    const float* Bb = B + (long)blockIdx.x * 128 * K;

    const int lr = tid >> 2;          // 0..63 row for loading
    const int lc = (tid & 3) << 2;    // 0,4,8,12 col for loading
    const int tr = (tid >> 4) << 3;   // 0..120 compute row base
    const int tc = (tid & 15) << 3;   // 0..120 compute col base

    float acc[8][8];
#pragma unroll
    for (int i = 0; i < 8; i++)
#pragma unroll
        for (int j = 0; j < 8; j++) acc[i][j] = 0.0f;

    for (int k0 = 0; k0 < K; k0 += 16) {
#pragma unroll
        for (int rr = 0; rr < 2; rr++) {
            int row = lr + rr * 64;
            float4 va = *reinterpret_cast<const float4*>(Ab + (long)row * K + k0 + lc);
            As[lc + 0][row] = va.x; As[lc + 1][row] = va.y;
            As[lc + 2][row] = va.z; As[lc + 3][row] = va.w;
            float4 vb = *reinterpret_cast<const float4*>(Bb + (long)row * K + k0 + lc);
            Bs[lc + 0][row] = vb.x; Bs[lc + 1][row] = vb.y;
            Bs[lc + 2][row] = vb.z; Bs[lc + 3][row] = vb.w;
        }
        __syncthreads();
#pragma unroll
        for (int kk = 0; kk < 16; kk++) {
            float4 a0 = *reinterpret_cast<const float4*>(&As[kk][tr]);
            float4 a1 = *reinterpret_cast<const float4*>(&As[kk][tr + 4]);
            float4 b0 = *reinterpret_cast<const float4*>(&Bs[kk][tc]);
            float4 b1 = *reinterpret_cast<const float4*>(&Bs[kk][tc + 4]);
            float ra[8] = {a0.x, a0.y, a0.z, a0.w, a1.x, a1.y, a1.z, a1.w};
            float rb[8] = {b0.x, b0.y, b0.z, b0.w, b1.x, b1.y, b1.z, b1.w};
#pragma unroll
            for (int i = 0; i < 8; i++)
#pragma unroll
                for (int j = 0; j < 8; j++)
                    acc[i][j] = fmaf(ra[i], rb[j], acc[i][j]);
        }
        __syncthreads();
    }

    float* Cb = C + (long)(blockIdx.y * 128 + tr) * N + blockIdx.x * 128 + tc;
#pragma unroll
    for (int i = 0; i < 8; i++) {
        float4 c0 = make_float4(acc[i][0], acc[i][1], acc[i][2], acc[i][3]);
        float4 c1 = make_float4(acc[i][4], acc[i][5], acc[i][6], acc[i][7]);
        *reinterpret_cast<float4*>(Cb + (long)i * N) = c0;
        *reinterpret_cast<float4*>(Cb + (long)i * N + 4) = c1;
    }
}

// ===================== Phase 1: per-chunk (cumprod end, acc end) =====================
// One thread per (chunk, lane). lane = ((b*H + h)*HD + i); rem = lane % 2048 is the
// column within a D-sized split of proj.
__global__ void chunk_summary_kernel() {
    int idx = blockIdx.x * blockDim.x + threadIdx.x;
    if (idx >= NC_ * LANES_) return;
    int c = idx >> 12;          // / 4096
    int lane = idx & 4095;
    int b = lane >> 11;
    int rem = lane & 2047;

    const float* base = g_proj + (long)(b * S_ + c * C_) * N1_ + rem;
    float prefix = 1.0f, acc = 0.0f;
#pragma unroll 4
    for (int t = 0; t < C_; t++) {
        const float* r = base + (long)t * N1_;
        float kr = r[D_];
        float vr = r[2 * D_];
        float ar = r[3 * D_];
        float a = fminf(fmaxf(sigmoidf_(ar + 2.0f), 0.6f), 0.9995f);
        float u = tanhf(kr) * vr;
        prefix *= a;
        acc += u / fmaxf(prefix, 1e-6f);
    }
    g_Pc[idx] = prefix;
    g_Ac[idx] = acc;
}

// ===================== Phase 2: sequential chunk-level scan =====================
__global__ void chunk_state_kernel() {
    int lane = blockIdx.x * blockDim.x + threadIdx.x;
    if (lane >= LANES_) return;
    float state = 0.0f;
#pragma unroll
    for (int c = 0; c < NC_; c++) {
        int idx = c * LANES_ + lane;
        g_S0[idx] = state;
        state = g_Pc[idx] * (state + g_Ac[idx]);
    }
}

// ===================== Phase 3: per-element memory states =====================
__global__ void mem_kernel() {
    int idx = blockIdx.x * blockDim.x + threadIdx.x;
    if (idx >= NC_ * LANES_) return;
    int c = idx >> 12;
    int lane = idx & 4095;
    int b = lane >> 11;
    int rem = lane & 2047;

    const float* base = g_proj + (long)(b * S_ + c * C_) * N1_ + rem;
    float* mout = g_mem + (long)(b * S_ + c * C_) * D_ + rem;
    float state = g_S0[idx];
    float prefix = 1.0f, acc = 0.0f;
#pragma unroll 4
    for (int t = 0; t < C_; t++) {
        const float* r = base + (long)t * N1_;
        float kr = r[D_];
        float vr = r[2 * D_];
        float ar = r[3 * D_];
        float a = fminf(fmaxf(sigmoidf_(ar + 2.0f), 0.6f), 0.9995f);
        float u = tanhf(kr) * vr;
        prefix *= a;
        acc += u / fmaxf(prefix, 1e-6f);
        mout[(long)t * D_] = prefix * (state + acc);
    }
}

// ========== Phase 4: RMS-norm(q), gating, y = gate*(q*mem) + (1-gate)*v ==========
// One warp per (token m, head h): 32 lanes x 4 elements = 128 = HD_.
__global__ void finalize_kernel() {
    int w = (blockIdx.x * blockDim.x + threadIdx.x) >> 5;
    int lanei = threadIdx.x & 31;
    if (w >= M_ * H_) return;
    int m = w >> 4;
    int h = w & 15;
    int d = h * HD_ + lanei * 4;

    const float* row = g_proj + (long)m * N1_;
    float4 q4 = *reinterpret_cast<const float4*>(row + d);
    float ss = q4.x * q4.x + q4.y * q4.y + q4.z * q4.z + q4.w * q4.w;
#pragma unroll
    for (int off = 16; off; off >>= 1)
        ss += __shfl_xor_sync(0xffffffffu, ss, off);
    float scale = rsqrtf(ss * (1.0f / 128.0f) + RMS_EPS);

    float4 v4 = *reinterpret_cast<const float4*>(row + 2 * D_ + d);
    float4 g4 = *reinterpret_cast<const float4*>(row + 4 * D_ + d);
    float4 mm = *reinterpret_cast<const float4*>(g_mem + (long)m * D_ + d);

    float4 y;
    {
        float gt = sigmoidf_(g4.x);
        y.x = gt * (q4.x * scale * mm.x) + (1.0f - gt) * v4.x;
        gt = sigmoidf_(g4.y);
        y.y = gt * (q4.y * scale * mm.y) + (1.0f - gt) * v4.y;
        gt = sigmoidf_(g4.z);
        y.z = gt * (q4.z * scale * mm.z) + (1.0f - gt) * v4.z;
        gt = sigmoidf_(g4.w);
        y.w = gt * (q4.w * scale * mm.w) + (1.0f - gt) * v4.w;
    }
    *reinterpret_cast<float4*>(g_y + (long)m * D_ + d) = y;
}

// ================================ launcher ================================
extern "C" void kernel_launch(void* const* d_in, const int* in_sizes, int n_in,
                              void* d_out, int out_size) {
    const float* x     = (const float*)d_in[0];   // [2,4096,2048]
    const float* w_in  = (const float*)d_in[1];   // [10240,2048]
    const float* w_out = (const float*)d_in[2];   // [2048,2048]
    float* out = (float*)d_out;                   // [2,4096,2048]

    float *proj_p, *mem_p, *y_p;
    cudaGetSymbolAddress((void**)&proj_p, g_proj);
    cudaGetSymbolAddress((void**)&mem_p, g_mem);
    cudaGetSymbolAddress((void**)&y_p, g_y);
    (void)mem_p;

    // GEMM1: proj = x @ w_in^T
    {
        dim3 grid(N1_ / 128, M_ / 128);
        sgemm_nt<<<grid, 256>>>(x, w_in, proj_p, M_, N1_, D_);
    }
    // Scan pipeline
    chunk_summary_kernel<<<(NC_ * LANES_) / 256, 256>>>();
    chunk_state_kernel<<<LANES_ / 256, 256>>>();
    mem_kernel<<<(NC_ * LANES_) / 256, 256>>>();
    finalize_kernel<<<(M_ * H_ * 32) / 256, 256>>>();
    // GEMM2: out = y @ w_out^T
    {
        dim3 grid(D_ / 128, M_ / 128);
        sgemm_nt<<<grid, 256>>>(y_p, w_out, out, M_, D_, D_);
    }
}

// round 9
// speedup vs baseline: 3.2647x; 3.2647x over previous
#include <cuda_runtime.h>
#include <math.h>
#include <stdint.h>

// Problem constants
#define B_    2
#define S_    4096
#define D_    2048
#define H_    16
#define HD_   128
#define C_    64
#define NC_   64
#define M_    (B_*S_)        // 8192 tokens
#define N1_   (5*D_)         // 10240
#define LANES_ (B_*H_*HD_)   // 4096
#define RMS_EPS 1.1920928955078125e-07f

// -------- scratch (static device globals; no runtime allocation) --------
__device__ float g_proj[M_*(size_t)N1_];   // [8192,10240] projection
__device__ float g_mem [M_*(size_t)D_];    // memory states [B*S, D]
__device__ float g_y   [M_*(size_t)D_];    // gated output  [B*S, D]
__device__ float g_Pc  [NC_*LANES_];       // per-chunk cumprod end
__device__ float g_Ac  [NC_*LANES_];       // per-chunk acc end
__device__ float g_S0  [NC_*LANES_];       // chunk-start states

__device__ __forceinline__ float sigmoidf_(float x) {
    return 1.0f / (1.0f + expf(-x));
}

// ===================== mma.sync tf32 GEMM (legacy tensor path) =====================
// C[M,N] = A[M,K] @ B[N,K]^T, fp32 in/out, tf32 mma.sync (m16n8k8) compute.
// BM=128 x BN=128 x BK=32, 256 threads (8 warps: 2x4), warp tile 64x32,
// double-buffered cp.async, SMEM rows padded to 36 floats (conflict-free frags).

#define BM 128
#define BN 128
#define BK 32
#define PAD_ROW 36                       // BK + 4
#define AS_F (BM*PAD_ROW)                // floats per A stage
#define BS_F (BN*PAD_ROW)                // floats per B stage
#define SMEM_BYTES (2*(AS_F+BS_F)*4)     // 73728

#define CP_ASYNC16(dst, src) \
    asm volatile("cp.async.cg.shared.global [%0], [%1], 16;" \
                 :: "r"(dst), "l"(src) : "memory")
#define CP_COMMIT() asm volatile("cp.async.commit_group;" ::: "memory")
#define CP_WAIT0()  asm volatile("cp.async.wait_group 0;" ::: "memory")

static __device__ __forceinline__ uint32_t f2tf32(float x) {
    uint32_t r;
    asm("cvt.rna.tf32.f32 %0, %1;" : "=r"(r) : "f"(x));
    return r;
}

static __device__ __forceinline__ void mma_tf32(float* c, const uint32_t* a,
                                                const uint32_t* b) {
    asm volatile(
        "mma.sync.aligned.m16n8k8.row.col.f32.tf32.tf32.f32 "
        "{%0,%1,%2,%3}, {%4,%5,%6,%7}, {%8,%9}, {%0,%1,%2,%3};"
        : "+f"(c[0]), "+f"(c[1]), "+f"(c[2]), "+f"(c[3])
        : "r"(a[0]), "r"(a[1]), "r"(a[2]), "r"(a[3]), "r"(b[0]), "r"(b[1]));
}

__global__ void __launch_bounds__(256, 2)
gemm_mma(const float* __restrict__ A, const float* __restrict__ Bmat,
         float* __restrict__ C, int M, int N, int K) {
    extern __shared__ float smemf[];
    const int tid = threadIdx.x;
    const int wid = tid >> 5;
    const int lane = tid & 31;
    const int g = lane >> 2;           // group id (0..7)
    const int t = lane & 3;            // thread-in-group (0..3)
    const int warp_m = wid >> 2;       // 0..1
    const int warp_n = wid & 3;        // 0..3

    const long Arow0 = (long)blockIdx.y * BM;
    const long Brow0 = (long)blockIdx.x * BN;
    const int ntiles = K / BK;

    float acc[4][4][4];
#pragma unroll
    for (int mt = 0; mt < 4; mt++)
#pragma unroll
        for (int nt = 0; nt < 4; nt++)
#pragma unroll
            for (int r = 0; r < 4; r++) acc[mt][nt][r] = 0.0f;

    // stage load: 1024 float4 per matrix / 256 threads = 4 each
    auto load_tile = [&](int s, int kt) {
        float* Ast = smemf + s * AS_F;
        float* Bst = smemf + 2 * AS_F + s * BS_F;
        const float* Asrc = A + Arow0 * K + (long)kt * BK;
        const float* Bsrc = Bmat + Brow0 * K + (long)kt * BK;
#pragma unroll
        for (int i = 0; i < 4; i++) {
            int ci = tid + i * 256;
            int row = ci >> 3;
            int col = (ci & 7) << 2;
            uint32_t da = (uint32_t)__cvta_generic_to_shared(Ast + row * PAD_ROW + col);
            CP_ASYNC16(da, Asrc + (long)row * K + col);
            uint32_t db = (uint32_t)__cvta_generic_to_shared(Bst + row * PAD_ROW + col);
            CP_ASYNC16(db, Bsrc + (long)row * K + col);
        }
        CP_COMMIT();
    };

    load_tile(0, 0);

    for (int kt = 0; kt < ntiles; kt++) {
        int buf = kt & 1;
        CP_WAIT0();
        __syncthreads();
        if (kt + 1 < ntiles) load_tile(buf ^ 1, kt + 1);

        const float* Asb = smemf + buf * AS_F;
        const float* Bsb = smemf + 2 * AS_F + buf * BS_F;
#pragma unroll
        for (int ks = 0; ks < 4; ks++) {
            const int k8 = ks * 8;
            uint32_t af[4][4], bf[4][2];
#pragma unroll
            for (int mt = 0; mt < 4; mt++) {
                int r0 = warp_m * 64 + mt * 16 + g;
                af[mt][0] = f2tf32(Asb[r0 * PAD_ROW + k8 + t]);
                af[mt][1] = f2tf32(Asb[(r0 + 8) * PAD_ROW + k8 + t]);
                af[mt][2] = f2tf32(Asb[r0 * PAD_ROW + k8 + t + 4]);
                af[mt][3] = f2tf32(Asb[(r0 + 8) * PAD_ROW + k8 + t + 4]);
            }
#pragma unroll
            for (int nt = 0; nt < 4; nt++) {
                int n0 = warp_n * 32 + nt * 8 + g;
                bf[nt][0] = f2tf32(Bsb[n0 * PAD_ROW + k8 + t]);
                bf[nt][1] = f2tf32(Bsb[n0 * PAD_ROW + k8 + t + 4]);
            }
#pragma unroll
            for (int mt = 0; mt < 4; mt++)
#pragma unroll
                for (int nt = 0; nt < 4; nt++)
                    mma_tf32(acc[mt][nt], af[mt], bf[nt]);
        }
        __syncthreads();
    }

    // epilogue: c0/c1 at (g, 2t/2t+1), c2/c3 at (g+8, ...)
#pragma unroll
    for (int mt = 0; mt < 4; mt++) {
#pragma unroll
        for (int nt = 0; nt < 4; nt++) {
            long row = Arow0 + warp_m * 64 + mt * 16 + g;
            long col = Brow0 + warp_n * 32 + nt * 8 + 2 * t;
            *reinterpret_cast<float2*>(C + row * N + col) =
                make_float2(acc[mt][nt][0], acc[mt][nt][1]);
            *reinterpret_cast<float2*>(C + (row + 8) * N + col) =
                make_float2(acc[mt][nt][2], acc[mt][nt][3]);
        }
    }
}

// ===================== Phase 1: per-chunk (cumprod end, acc end) =====================
__global__ void chunk_summary_kernel() {
    int idx = blockIdx.x * blockDim.x + threadIdx.x;
    if (idx >= NC_ * LANES_) return;
    int c = idx >> 12;
    int lane = idx & 4095;
    int b = lane >> 11;
    int rem = lane & 2047;

    const float* base = g_proj + (long)(b * S_ + c * C_) * N1_ + rem;
    float prefix = 1.0f, acc = 0.0f;
#pragma unroll 4
    for (int t = 0; t < C_; t++) {
        const float* r = base + (long)t * N1_;
        float kr = r[D_];
        float vr = r[2 * D_];
        float ar = r[3 * D_];
        float a = fminf(fmaxf(sigmoidf_(ar + 2.0f), 0.6f), 0.9995f);
        float u = tanhf(kr) * vr;
        prefix *= a;
        acc += u / fmaxf(prefix, 1e-6f);
    }
    g_Pc[idx] = prefix;
    g_Ac[idx] = acc;
}

// ===================== Phase 2: sequential chunk-level scan =====================
__global__ void chunk_state_kernel() {
    int lane = blockIdx.x * blockDim.x + threadIdx.x;
    if (lane >= LANES_) return;
    float state = 0.0f;
#pragma unroll
    for (int c = 0; c < NC_; c++) {
        int idx = c * LANES_ + lane;
        g_S0[idx] = state;
        state = g_Pc[idx] * (state + g_Ac[idx]);
    }
}

// ===================== Phase 3: per-element memory states =====================
__global__ void mem_kernel() {
    int idx = blockIdx.x * blockDim.x + threadIdx.x;
    if (idx >= NC_ * LANES_) return;
    int c = idx >> 12;
    int lane = idx & 4095;
    int b = lane >> 11;
    int rem = lane & 2047;

    const float* base = g_proj + (long)(b * S_ + c * C_) * N1_ + rem;
    float* mout = g_mem + (long)(b * S_ + c * C_) * D_ + rem;
    float state = g_S0[idx];
    float prefix = 1.0f, acc = 0.0f;
#pragma unroll 4
    for (int t = 0; t < C_; t++) {
        const float* r = base + (long)t * N1_;
        float kr = r[D_];
        float vr = r[2 * D_];
        float ar = r[3 * D_];
        float a = fminf(fmaxf(sigmoidf_(ar + 2.0f), 0.6f), 0.9995f);
        float u = tanhf(kr) * vr;
        prefix *= a;
        acc += u / fmaxf(prefix, 1e-6f);
        mout[(long)t * D_] = prefix * (state + acc);
    }
}

// ========== Phase 4: RMS-norm(q), gating, y = gate*(q*mem) + (1-gate)*v ==========
__global__ void finalize_kernel() {
    int w = (blockIdx.x * blockDim.x + threadIdx.x) >> 5;
    int lanei = threadIdx.x & 31;
    if (w >= M_ * H_) return;
    int m = w >> 4;
    int h = w & 15;
    int d = h * HD_ + lanei * 4;

    const float* row = g_proj + (long)m * N1_;
    float4 q4 = *reinterpret_cast<const float4*>(row + d);
    float ss = q4.x * q4.x + q4.y * q4.y + q4.z * q4.z + q4.w * q4.w;
#pragma unroll
    for (int off = 16; off; off >>= 1)
        ss += __shfl_xor_sync(0xffffffffu, ss, off);
    float scale = rsqrtf(ss * (1.0f / 128.0f) + RMS_EPS);

    float4 v4 = *reinterpret_cast<const float4*>(row + 2 * D_ + d);
    float4 g4 = *reinterpret_cast<const float4*>(row + 4 * D_ + d);
    float4 mm = *reinterpret_cast<const float4*>(g_mem + (long)m * D_ + d);

    float4 y;
    {
        float gt = sigmoidf_(g4.x);
        y.x = gt * (q4.x * scale * mm.x) + (1.0f - gt) * v4.x;
        gt = sigmoidf_(g4.y);
        y.y = gt * (q4.y * scale * mm.y) + (1.0f - gt) * v4.y;
        gt = sigmoidf_(g4.z);
        y.z = gt * (q4.z * scale * mm.z) + (1.0f - gt) * v4.z;
        gt = sigmoidf_(g4.w);
        y.w = gt * (q4.w * scale * mm.w) + (1.0f - gt) * v4.w;
    }
    *reinterpret_cast<float4*>(g_y + (long)m * D_ + d) = y;
}

// ================================ launcher ================================
extern "C" void kernel_launch(void* const* d_in, const int* in_sizes, int n_in,
                              void* d_out, int out_size) {
    const float* x     = (const float*)d_in[0];   // [2,4096,2048]
    const float* w_in  = (const float*)d_in[1];   // [10240,2048]
    const float* w_out = (const float*)d_in[2];   // [2048,2048]
    float* out = (float*)d_out;                   // [2,4096,2048]

    float *proj_p, *y_p;
    cudaGetSymbolAddress((void**)&proj_p, g_proj);
    cudaGetSymbolAddress((void**)&y_p, g_y);

    cudaFuncSetAttribute(gemm_mma, cudaFuncAttributeMaxDynamicSharedMemorySize,
                         SMEM_BYTES);

    // GEMM1: proj = x @ w_in^T   (tf32 mma.sync)
    {
        dim3 grid(N1_ / BN, M_ / BM);   // (80, 64)
        gemm_mma<<<grid, 256, SMEM_BYTES>>>(x, w_in, proj_p, M_, N1_, D_);
    }
    // Scan pipeline
    chunk_summary_kernel<<<(NC_ * LANES_) / 256, 256>>>();
    chunk_state_kernel<<<LANES_ / 256, 256>>>();
    mem_kernel<<<(NC_ * LANES_) / 256, 256>>>();
    finalize_kernel<<<(M_ * H_ * 32) / 256, 256>>>();
    // GEMM2: out = y @ w_out^T
    {
        dim3 grid(D_ / BN, M_ / BM);    // (16, 64)
        gemm_mma<<<grid, 256, SMEM_BYTES>>>(y_p, w_out, out, M_, D_, D_);
    }
}